// round 6
// baseline (speedup 1.0000x reference)
#include <cuda_runtime.h>
#include <cuda_bf16.h>
#include <cstdint>
#include <cstddef>

// out[b,s,d] = 16 * sum_v x[b,s,v]*emb[v,d] + pos_enc[s,d]*any(x[b,s,:])
// GEMM: M=8192 (b*s), N=256 (d), K=8192 (v), extended K'=16384 via hi/lo
// bf16 split of emb*16 (B'[n,2v]=hi, B'[n,2v+1]=lo; A duplicated).
// NOTE: harness lowers PTX to compute_103 (no 'a') -> tcgen05 unavailable.
// This uses the baseline path: mma.sync bf16 + ldmatrix + cp.async.

static constexpr int DIM_S = 1024;
static constexpr int DIM_V = 8192;
static constexpr int DIM_D = 256;

static constexpr int KP     = 2 * DIM_V;   // 16384
static constexpr int TM     = 64;          // CTA M tile
static constexpr int TKB    = 64;          // K' per stage
static constexpr int NSTAGE = KP / TKB;    // 256
static constexpr int RING   = 4;

static constexpr uint32_t A_BYTES  = TM * 128;      // 8 KB  (64 rows x 128B)
static constexpr uint32_t B_BYTES  = DIM_D * 128;   // 32 KB (256 rows x 128B)
static constexpr uint32_t ST_BYTES = A_BYTES + B_BYTES;          // 40 KB
static constexpr uint32_t SMEM_DYN = RING * ST_BYTES + 1024;     // +align pad

// Transposed hi/lo-interleaved table: [D=256][K'=16384] bf16 (8 MB), *16 folded.
__device__ __align__(128) __nv_bfloat16 g_embT[(size_t)DIM_D * KP];

__device__ __forceinline__ uint32_t smem_u32(const void* p) {
    return (uint32_t)__cvta_generic_to_shared(p);
}
__device__ __forceinline__ uint32_t sw128(uint32_t off) {
    return off ^ ((off >> 3) & 0x70u);
}
__device__ __forceinline__ uint32_t packdup_bf16(int v) {
    __nv_bfloat16 b = __float2bfloat16((float)v);
    uint32_t u = (uint32_t)__bfloat16_as_ushort(b);
    return u | (u << 16);
}

// ---------------------------------------------------------------------------
// Prep: emb fp32 -> (hi, lo) bf16 of (emb*16), transpose to [d][2v+t].
// ---------------------------------------------------------------------------
__global__ void prep_split_transpose(const float* __restrict__ emb) {
    __shared__ float tile[32][33];
    const int v0 = blockIdx.x * 32;
    const int d0 = blockIdx.y * 32;
    const int t  = threadIdx.x;
#pragma unroll
    for (int it = 0; it < 4; ++it) {
        int idx = t + it * 256, i = idx >> 5, j = idx & 31;
        tile[i][j] = emb[(size_t)(v0 + i) * DIM_D + d0 + j];
    }
    __syncthreads();
#pragma unroll
    for (int it = 0; it < 4; ++it) {
        int idx = t + it * 256, dl = idx >> 5, vl = idx & 31;
        float e = tile[vl][dl] * 16.0f;
        __nv_bfloat16 h = __float2bfloat16(e);
        __nv_bfloat16 l = __float2bfloat16(e - __bfloat162float(h));
        __nv_bfloat162 pr; pr.x = h; pr.y = l;
        *reinterpret_cast<__nv_bfloat162*>(
            &g_embT[(size_t)(d0 + dl) * KP + 2 * (size_t)(v0 + vl)]) = pr;
    }
}

// ---------------------------------------------------------------------------
// Producer helpers
// ---------------------------------------------------------------------------
__device__ __forceinline__ void load_a(int4* va, const int* __restrict__ x,
                                       int m0, int stage, int t) {
    const int4* xr = reinterpret_cast<const int4*>(x);
#pragma unroll
    for (int i = 0; i < 2; ++i) {
        int idx = t + i * 256;
        int row = idx >> 3, q = idx & 7;            // 64 rows x 8 int4
        va[i] = xr[(size_t)(m0 + row) * (DIM_V / 4) + (size_t)stage * 8 + q];
    }
}

__device__ __forceinline__ void store_a(const int4* va, uint32_t abase,
                                        int t, int* flags) {
#pragma unroll
    for (int i = 0; i < 2; ++i) {
        int idx = t + i * 256;
        int row = idx >> 3, q = idx & 7;
        int4 v = va[i];
        if (v.x | v.y | v.z | v.w) flags[row] = 1;   // benign same-value race
        uint32_t u0 = packdup_bf16(v.x), u1 = packdup_bf16(v.y);
        uint32_t u2 = packdup_bf16(v.z), u3 = packdup_bf16(v.w);
        uint32_t dst = abase + sw128((uint32_t)row * 128u + (uint32_t)q * 16u);
        asm volatile("st.shared.v4.b32 [%0], {%1,%2,%3,%4};"
                     :: "r"(dst), "r"(u0), "r"(u1), "r"(u2), "r"(u3));
    }
}

__device__ __forceinline__ void issue_b(uint32_t bbase, int stage, int t) {
    const char* bsrc = reinterpret_cast<const char*>(g_embT);
#pragma unroll
    for (int i = 0; i < 8; ++i) {
        int idx = t + i * 256;
        int row = idx >> 3, seg = idx & 7;          // 256 rows x 8 x 16B
        uint32_t dst = bbase + sw128((uint32_t)row * 128u + (uint32_t)seg * 16u);
        const void* src = bsrc + (size_t)row * (KP * 2) + (size_t)stage * 128 + seg * 16;
        asm volatile("cp.async.cg.shared.global [%0], [%1], 16;" :: "r"(dst), "l"(src));
    }
}

// ---------------------------------------------------------------------------
// GEMM: 128 CTAs x 256 thr; CTA tile 64x256; warp tile 32x64; K'=16384.
// ---------------------------------------------------------------------------
__global__ __launch_bounds__(256, 1)
void multihot_gemm(const int* __restrict__ x, const float* __restrict__ pos,
                   float* __restrict__ out) {
    extern __shared__ char dynsm[];
    __shared__ int flags[TM];

    const int t = threadIdx.x;
    const int wid = t >> 5, lane = t & 31;
    const int m0 = blockIdx.x * TM;
    const int wm = wid & 1, wn = wid >> 1;

    const uint32_t base = (smem_u32(dynsm) + 1023u) & ~1023u;

    for (int i = t; i < TM; i += 256) flags[i] = 0;
    __syncthreads();

    float acc[2][8][4];
#pragma unroll
    for (int a = 0; a < 2; ++a)
#pragma unroll
        for (int b = 0; b < 8; ++b)
#pragma unroll
            for (int c = 0; c < 4; ++c) acc[a][b][c] = 0.0f;

    // --- prologue: stages 0..2 ---
    int4 va[2];
    load_a(va, x, m0, 0, t);
#pragma unroll
    for (int s = 0; s < RING - 1; ++s) {
        uint32_t ab = base + (uint32_t)s * ST_BYTES;
        store_a(va, ab, t, flags);
        issue_b(ab + A_BYTES, s, t);
        asm volatile("cp.async.commit_group;" ::: "memory");
        load_a(va, x, m0, s + 1, t);
    }
    // va now holds A(stage 3)

    // --- per-lane ldmatrix address precompute ---
    const uint32_t rxor = (uint32_t)(lane & 7) << 4;
    // A: lanes 0-15 rows 0..15, 16-31 same rows at +16B (k8 half)
    const uint32_t a_khalf = (uint32_t)(lane >> 4) << 4;
    uint32_t a_row_addr[2];
#pragma unroll
    for (int mt = 0; mt < 2; ++mt) {
        int row = wm * 32 + mt * 16 + (lane & 15);
        a_row_addr[mt] = base /*stage added later*/ + (uint32_t)row * 128u;
    }
    // B: lanes 0-7 rows n0..7 k0 | 8-15 rows n0..7 k8 | 16-23 n8..15 k0 | 24-31 n8..15 k8
    const uint32_t b_khalf = (uint32_t)((lane >> 3) & 1) << 4;
    uint32_t b_row_addr[4];
#pragma unroll
    for (int ntp = 0; ntp < 4; ++ntp) {
        int nrow = wn * 64 + ntp * 16 + (lane & 7) + ((lane >> 4) << 3);
        b_row_addr[ntp] = base + A_BYTES + (uint32_t)nrow * 128u;
    }

    // --- mainloop ---
#pragma unroll 1
    for (int k = 0; k < NSTAGE; ++k) {
        asm volatile("cp.async.wait_group %0;" :: "n"(RING - 2) : "memory");
        __syncthreads();

        if (k + RING - 1 < NSTAGE) {
            uint32_t ab = base + (uint32_t)((k + RING - 1) & (RING - 1)) * ST_BYTES;
            store_a(va, ab, t, flags);
            issue_b(ab + A_BYTES, k + RING - 1, t);
        }
        if (k + RING < NSTAGE) load_a(va, x, m0, k + RING, t);
        asm volatile("cp.async.commit_group;" ::: "memory");

        const uint32_t soff = (uint32_t)(k & (RING - 1)) * ST_BYTES;
#pragma unroll
        for (int ks = 0; ks < 4; ++ks) {
            const uint32_t kb = (uint32_t)ks * 32u;
            uint32_t af[2][4];
#pragma unroll
            for (int mt = 0; mt < 2; ++mt) {
                uint32_t addr = a_row_addr[mt] + soff + ((kb + a_khalf) ^ rxor);
                asm volatile("ldmatrix.sync.aligned.m8n8.x4.shared.b16 "
                             "{%0,%1,%2,%3}, [%4];"
                             : "=r"(af[mt][0]), "=r"(af[mt][1]),
                               "=r"(af[mt][2]), "=r"(af[mt][3])
                             : "r"(addr));
            }
            uint32_t bf[4][4];
#pragma unroll
            for (int ntp = 0; ntp < 4; ++ntp) {
                uint32_t addr = b_row_addr[ntp] + soff + ((kb + b_khalf) ^ rxor);
                asm volatile("ldmatrix.sync.aligned.m8n8.x4.shared.b16 "
                             "{%0,%1,%2,%3}, [%4];"
                             : "=r"(bf[ntp][0]), "=r"(bf[ntp][1]),
                               "=r"(bf[ntp][2]), "=r"(bf[ntp][3])
                             : "r"(addr));
            }
#pragma unroll
            for (int mt = 0; mt < 2; ++mt) {
#pragma unroll
                for (int nt = 0; nt < 8; ++nt) {
                    float* c = acc[mt][nt];
                    const uint32_t* bp = &bf[nt >> 1][(nt & 1) * 2];
                    asm volatile(
                        "mma.sync.aligned.m16n8k16.row.col.f32.bf16.bf16.f32 "
                        "{%0,%1,%2,%3}, {%4,%5,%6,%7}, {%8,%9}, {%0,%1,%2,%3};"
                        : "+f"(c[0]), "+f"(c[1]), "+f"(c[2]), "+f"(c[3])
                        : "r"(af[mt][0]), "r"(af[mt][1]),
                          "r"(af[mt][2]), "r"(af[mt][3]),
                          "r"(bp[0]), "r"(bp[1]));
                }
            }
        }
    }

    // --- epilogue: out = acc + pos*any_tok  (x16 folded into g_embT) ---
    const int lr = lane >> 2;
    const int lc = (lane & 3) * 2;
#pragma unroll
    for (int mt = 0; mt < 2; ++mt) {
        const int rbase = wm * 32 + mt * 16 + lr;
#pragma unroll
        for (int half = 0; half < 2; ++half) {
            const int rl = rbase + half * 8;
            const int grow = m0 + rl;
            const float tokf = flags[rl] ? 1.0f : 0.0f;
            const float* prow = pos + (size_t)(grow & (DIM_S - 1)) * DIM_D;
            float* orow = out + (size_t)grow * DIM_D;
#pragma unroll
            for (int nt = 0; nt < 8; ++nt) {
                const int col = wn * 64 + nt * 8 + lc;
                float2 pv = *reinterpret_cast<const float2*>(prow + col);
                float2 ov;
                ov.x = acc[mt][nt][half * 2 + 0] + pv.x * tokf;
                ov.y = acc[mt][nt][half * 2 + 1] + pv.y * tokf;
                *reinterpret_cast<float2*>(orow + col) = ov;
            }
        }
    }
}

// ---------------------------------------------------------------------------
extern "C" void kernel_launch(void* const* d_in, const int* in_sizes, int n_in,
                              void* d_out, int out_size) {
    (void)in_sizes; (void)n_in; (void)out_size;
    const int*   x   = (const int*)d_in[0];     // [8,1024,8192] int32
    const float* emb = (const float*)d_in[1];   // [8192,256] f32
    const float* pos = (const float*)d_in[2];   // [1,1024,256] f32
    float* out = (float*)d_out;                 // [8,1024,256] f32

    cudaFuncSetAttribute(multihot_gemm,
                         cudaFuncAttributeMaxDynamicSharedMemorySize, SMEM_DYN);

    prep_split_transpose<<<dim3(DIM_V / 32, DIM_D / 32), 256>>>(emb);
    multihot_gemm<<<(8 * DIM_S) / TM, 256, SMEM_DYN>>>(x, pos, out);
}